// round 1
// baseline (speedup 1.0000x reference)
#include <cuda_runtime.h>

// Problem constants (fixed by the reference)
static constexpr int       BS    = 64;
static constexpr int       KP1   = 8193;        // K + 1
static constexpr int       FEAT  = 128;
static constexpr long long NDATA = 1000000LL;
static constexpr float     TINV  = 1.0f / 0.07f;

// d_out layout: out_s | out_t | mem_s_new | mem_t_new  (all float32)
static constexpr long long PER       = (long long)BS * KP1;        // 524,352
static constexpr long long OUT_S_OFF = 0;
static constexpr long long OUT_T_OFF = PER;
static constexpr long long MEM_S_OFF = 2 * PER;
static constexpr long long MEM_T_OFF = MEM_S_OFF + NDATA * FEAT;

// Scratch (no allocations allowed): Z accumulators + index-dtype flag
__device__ double g_sum[2];
__device__ int    g_idx64;

// ---------------------------------------------------------------------------
// Init: zero accumulators and detect whether idx/sample_idx are i64 or i32.
// JAX without x64 downcasts the reference's int64 to int32; probe the words.
// If data is true int64 (<2^31 values), every odd 32-bit word is 0.
// ---------------------------------------------------------------------------
__global__ void k_init(const int* __restrict__ sidx_as_i32) {
    if (threadIdx.x == 0) {
        g_sum[0] = 0.0;
        g_sum[1] = 0.0;
        bool i64 = (sidx_as_i32[1] == 0) && (sidx_as_i32[3] == 0) &&
                   (sidx_as_i32[5] == 0) && (sidx_as_i32[7] == 0);
        g_idx64 = i64 ? 1 : 0;
    }
}

__device__ __forceinline__ long long load_index(const void* p, long long i) {
    return g_idx64 ? ((const long long*)p)[i]
                   : (long long)((const int*)p)[i];
}

// ---------------------------------------------------------------------------
// Contrast: one warp per (b, k) dot product, both contrasts in one grid.
// which==0 : out_s = <memory_t[row], feat_s[b]>
// which==1 : out_t = <memory_s[row], feat_t[b]>
// Stores raw exp values; accumulates per-contrast sum for Z.
// Grid is sized so each block's 8 warps share a single `which`.
// ---------------------------------------------------------------------------
__global__ void __launch_bounds__(256)
k_contrast(const float* __restrict__ mem_s, const float* __restrict__ mem_t,
           const float* __restrict__ feat_s, const float* __restrict__ feat_t,
           const void*  __restrict__ sample_idx, float* __restrict__ out)
{
    __shared__ float warp_e[8];
    const int warp = threadIdx.x >> 5;
    const int lane = threadIdx.x & 31;

    long long item  = (long long)blockIdx.x * 8 + warp;     // < 2*PER by grid sizing
    const int which = (item >= PER) ? 1 : 0;                 // uniform per block (PER % 8 == 0)
    long long local = item - (long long)which * PER;
    const int b = (int)(local / KP1);
    const int k = (int)(local % KP1);

    const long long row = load_index(sample_idx, (long long)b * KP1 + k);

    const float* __restrict__ mem  = which ? mem_s  : mem_t;
    const float* __restrict__ feat = which ? feat_t : feat_s;

    const float4 m = *(const float4*)(mem  + row * FEAT + lane * 4);
    const float4 f = *(const float4*)(feat + (long long)b * FEAT + lane * 4);

    float d = m.x * f.x + m.y * f.y + m.z * f.z + m.w * f.w;
    #pragma unroll
    for (int o = 16; o; o >>= 1) d += __shfl_xor_sync(0xffffffffu, d, o);

    float e = __expf(fminf(d * TINV, 50.0f));
    if (lane == 0) {
        out[(which ? OUT_T_OFF : OUT_S_OFF) + local] = e;
        warp_e[warp] = e;
    }
    __syncthreads();
    if (threadIdx.x == 0) {
        float s = 0.0f;
        #pragma unroll
        for (int i = 0; i < 8; i++) s += warp_e[i];
        atomicAdd(&g_sum[which], (double)s);
    }
}

// ---------------------------------------------------------------------------
// Scale: out /= Z, where Z = mean * N_DATA  =>  out *= PER / (sum * N_DATA)
// ---------------------------------------------------------------------------
__global__ void __launch_bounds__(256)
k_scale(float* __restrict__ out)
{
    long long i = (long long)blockIdx.x * blockDim.x + threadIdx.x;
    if (i >= 2 * PER) return;
    const int which = (i >= PER) ? 1 : 0;
    const float inv = (float)((double)PER / (g_sum[which] * (double)NDATA));
    out[i] *= inv;
}

// ---------------------------------------------------------------------------
// Bank copy: both 512 MB banks, float4 grid-stride. Pure HBM stream.
// ---------------------------------------------------------------------------
__global__ void __launch_bounds__(256)
k_copy(const float4* __restrict__ src_s, const float4* __restrict__ src_t,
       float4* __restrict__ dst_s, float4* __restrict__ dst_t, long long n4)
{
    const long long stride = (long long)gridDim.x * blockDim.x;
    for (long long i = (long long)blockIdx.x * blockDim.x + threadIdx.x;
         i < n4; i += stride) {
        dst_s[i] = src_s[i];
        dst_t[i] = src_t[i];
    }
}

// ---------------------------------------------------------------------------
// Momentum update of the 64 touched rows (reads ORIGINAL bank from input,
// writes into the copied output bank — must run after k_copy).
// One block of 128 threads per (bank, b). pos = 0.5*mem + 0.5*feat, renorm.
// ---------------------------------------------------------------------------
__global__ void __launch_bounds__(128)
k_update(const float* __restrict__ mem_s, const float* __restrict__ mem_t,
         const float* __restrict__ feat_s, const float* __restrict__ feat_t,
         const void*  __restrict__ idx, float* __restrict__ out)
{
    const int bank = blockIdx.x >> 6;       // 0 = s-bank, 1 = t-bank
    const int b    = blockIdx.x & 63;
    const int t    = threadIdx.x;           // 0..127 (one dim each)

    const float* __restrict__ mem  = bank ? mem_t  : mem_s;
    const float* __restrict__ feat = bank ? feat_t : feat_s;
    float* __restrict__ dst = out + (bank ? MEM_T_OFF : MEM_S_OFF);

    const long long row = load_index(idx, b);
    const float v = mem[row * FEAT + t] * 0.5f + feat[(long long)b * FEAT + t] * 0.5f;

    float s = v * v;
    #pragma unroll
    for (int o = 16; o; o >>= 1) s += __shfl_xor_sync(0xffffffffu, s, o);
    __shared__ float ws[4];
    if ((t & 31) == 0) ws[t >> 5] = s;
    __syncthreads();
    const float tot = ws[0] + ws[1] + ws[2] + ws[3];
    const float inv = 1.0f / fmaxf(sqrtf(tot), 1e-12f);

    dst[row * FEAT + t] = v * inv;
}

// ---------------------------------------------------------------------------
extern "C" void kernel_launch(void* const* d_in, const int* in_sizes, int n_in,
                              void* d_out, int out_size)
{
    const float* feat_s     = (const float*)d_in[0];
    const float* feat_t     = (const float*)d_in[1];
    const void*  idx        = d_in[2];
    const void*  sample_idx = d_in[3];
    const float* mem_s      = (const float*)d_in[4];
    const float* mem_t      = (const float*)d_in[5];
    float* out = (float*)d_out;

    k_init<<<1, 32>>>((const int*)sample_idx);

    // 2*PER warps, 8 warps/block -> 131,088 blocks (exact, PER % 8 == 0)
    k_contrast<<<(unsigned)(2 * PER / 8), 256>>>(mem_s, mem_t, feat_s, feat_t,
                                                 sample_idx, out);

    k_scale<<<(unsigned)((2 * PER + 255) / 256), 256>>>(out);

    const long long n4 = NDATA * FEAT / 4;   // 32M float4 per bank
    k_copy<<<2368, 256>>>((const float4*)mem_s, (const float4*)mem_t,
                          (float4*)(out + MEM_S_OFF), (float4*)(out + MEM_T_OFF), n4);

    k_update<<<128, 128>>>(mem_s, mem_t, feat_s, feat_t, idx, out);
}

// round 2
// speedup vs baseline: 1.5038x; 1.5038x over previous
#include <cuda_runtime.h>

// Problem constants (fixed by the reference)
static constexpr int       BS    = 64;
static constexpr int       KP1   = 8193;        // K + 1
static constexpr int       FEAT  = 128;
static constexpr long long NDATA = 1000000LL;
static constexpr float     TINV  = 1.0f / 0.07f;

// d_out layout: out_s | out_t | mem_s_new | mem_t_new  (all float32)
static constexpr long long PER       = (long long)BS * KP1;        // 524,352
static constexpr long long OUT_S_OFF = 0;
static constexpr long long OUT_T_OFF = PER;
static constexpr long long MEM_S_OFF = 2 * PER;
static constexpr long long MEM_T_OFF = MEM_S_OFF + NDATA * FEAT;

static constexpr int UNROLL = 8;                // items per warp in k_contrast

// Scratch (no allocations allowed): Z accumulators + index-dtype flag
__device__ double g_sum[2];
__device__ int    g_idx64;

// ---------------------------------------------------------------------------
// Init: zero accumulators and detect whether idx/sample_idx are i64 or i32.
// JAX without x64 downcasts the reference's int64 to int32; probe odd words.
// ---------------------------------------------------------------------------
__global__ void k_init(const int* __restrict__ sidx_as_i32) {
    if (threadIdx.x == 0) {
        g_sum[0] = 0.0;
        g_sum[1] = 0.0;
        bool i64 = (sidx_as_i32[1] == 0) && (sidx_as_i32[3] == 0) &&
                   (sidx_as_i32[5] == 0) && (sidx_as_i32[7] == 0);
        g_idx64 = i64 ? 1 : 0;
    }
}

__device__ __forceinline__ long long load_index(const void* p, long long i) {
    return g_idx64 ? ((const long long*)p)[i]
                   : (long long)((const int*)p)[i];
}

// ---------------------------------------------------------------------------
// Contrast: each warp handles UNROLL consecutive items of the flattened
// [0, 2*PER) space. All UNROLL gather loads are issued before any reduction
// (MLP = UNROLL). No atomics here — raw exp values are stored; Z is computed
// by k_sum afterwards.
//   item <  PER : out_s = <memory_t[row], feat_s[b]>
//   item >= PER : out_t = <memory_s[row], feat_t[b]>
// ---------------------------------------------------------------------------
__global__ void __launch_bounds__(256)
k_contrast(const float* __restrict__ mem_s, const float* __restrict__ mem_t,
           const float* __restrict__ feat_s, const float* __restrict__ feat_t,
           const void*  __restrict__ sample_idx, float* __restrict__ out)
{
    const int warp = threadIdx.x >> 5;
    const int lane = threadIdx.x & 31;
    const long long base = ((long long)blockIdx.x * 8 + warp) * UNROLL;

    float4 m[UNROLL];
    int    whicha[UNROLL];
    unsigned locala[UNROLL];
    int    ba[UNROLL];

    // Phase 1: issue all gather loads (independent -> high MLP)
    #pragma unroll
    for (int u = 0; u < UNROLL; u++) {
        const long long item = base + u;
        const int w = (item >= PER) ? 1 : 0;
        const unsigned loc = (unsigned)(item - (long long)w * PER);
        const int b = (int)(loc / (unsigned)KP1);       // mul-shift, 32-bit
        const int k = (int)(loc % (unsigned)KP1);
        const long long row = load_index(sample_idx, (long long)b * KP1 + k);
        const float* __restrict__ mp = w ? mem_s : mem_t;
        m[u] = *(const float4*)(mp + row * FEAT + lane * 4);
        whicha[u] = w; locala[u] = loc; ba[u] = b;
    }

    // Phase 2: dot + warp reduce + exp + store
    #pragma unroll
    for (int u = 0; u < UNROLL; u++) {
        const float* __restrict__ fp = whicha[u] ? feat_t : feat_s;
        const float4 f = *(const float4*)(fp + (long long)ba[u] * FEAT + lane * 4);
        float d = m[u].x * f.x + m[u].y * f.y + m[u].z * f.z + m[u].w * f.w;
        #pragma unroll
        for (int o = 16; o; o >>= 1) d += __shfl_xor_sync(0xffffffffu, d, o);
        if (lane == 0) {
            out[(whicha[u] ? OUT_T_OFF : OUT_S_OFF) + locala[u]] =
                __expf(fminf(d * TINV, 50.0f));
        }
    }
}

// ---------------------------------------------------------------------------
// Sum: grid-stride over out[0 : PER) and out[PER : 2*PER) simultaneously,
// block-reduce, 2 atomics per block (~1K atomics total).
// ---------------------------------------------------------------------------
__global__ void __launch_bounds__(256)
k_sum(const float* __restrict__ out)
{
    double s0 = 0.0, s1 = 0.0;
    const long long stride = (long long)gridDim.x * blockDim.x;
    for (long long i = (long long)blockIdx.x * blockDim.x + threadIdx.x;
         i < PER; i += stride) {
        s0 += (double)out[i];
        s1 += (double)out[i + PER];
    }
    __shared__ double sh0[256], sh1[256];
    sh0[threadIdx.x] = s0; sh1[threadIdx.x] = s1;
    __syncthreads();
    for (int o = 128; o; o >>= 1) {
        if (threadIdx.x < o) {
            sh0[threadIdx.x] += sh0[threadIdx.x + o];
            sh1[threadIdx.x] += sh1[threadIdx.x + o];
        }
        __syncthreads();
    }
    if (threadIdx.x == 0) {
        atomicAdd(&g_sum[0], sh0[0]);
        atomicAdd(&g_sum[1], sh1[0]);
    }
}

// ---------------------------------------------------------------------------
// Scale: out /= Z, Z = mean * N_DATA  =>  out *= PER / (sum * N_DATA)
// ---------------------------------------------------------------------------
__global__ void __launch_bounds__(256)
k_scale(float* __restrict__ out)
{
    long long i = (long long)blockIdx.x * blockDim.x + threadIdx.x;
    if (i >= 2 * PER) return;
    const int which = (i >= PER) ? 1 : 0;
    const float inv = (float)((double)PER / (g_sum[which] * (double)NDATA));
    out[i] *= inv;
}

// ---------------------------------------------------------------------------
// Bank copy: both 512 MB banks, float4 grid-stride. Pure HBM stream (84% DRAM).
// ---------------------------------------------------------------------------
__global__ void __launch_bounds__(256)
k_copy(const float4* __restrict__ src_s, const float4* __restrict__ src_t,
       float4* __restrict__ dst_s, float4* __restrict__ dst_t, long long n4)
{
    const long long stride = (long long)gridDim.x * blockDim.x;
    for (long long i = (long long)blockIdx.x * blockDim.x + threadIdx.x;
         i < n4; i += stride) {
        dst_s[i] = src_s[i];
        dst_t[i] = src_t[i];
    }
}

// ---------------------------------------------------------------------------
// Momentum update of the 64 touched rows (reads ORIGINAL bank from input,
// writes into the copied output bank — must run after k_copy).
// ---------------------------------------------------------------------------
__global__ void __launch_bounds__(128)
k_update(const float* __restrict__ mem_s, const float* __restrict__ mem_t,
         const float* __restrict__ feat_s, const float* __restrict__ feat_t,
         const void*  __restrict__ idx, float* __restrict__ out)
{
    const int bank = blockIdx.x >> 6;       // 0 = s-bank, 1 = t-bank
    const int b    = blockIdx.x & 63;
    const int t    = threadIdx.x;           // 0..127

    const float* __restrict__ mem  = bank ? mem_t  : mem_s;
    const float* __restrict__ feat = bank ? feat_t : feat_s;
    float* __restrict__ dst = out + (bank ? MEM_T_OFF : MEM_S_OFF);

    const long long row = load_index(idx, b);
    const float v = mem[row * FEAT + t] * 0.5f + feat[(long long)b * FEAT + t] * 0.5f;

    float s = v * v;
    #pragma unroll
    for (int o = 16; o; o >>= 1) s += __shfl_xor_sync(0xffffffffu, s, o);
    __shared__ float ws[4];
    if ((t & 31) == 0) ws[t >> 5] = s;
    __syncthreads();
    const float tot = ws[0] + ws[1] + ws[2] + ws[3];
    const float inv = 1.0f / fmaxf(sqrtf(tot), 1e-12f);

    dst[row * FEAT + t] = v * inv;
}

// ---------------------------------------------------------------------------
extern "C" void kernel_launch(void* const* d_in, const int* in_sizes, int n_in,
                              void* d_out, int out_size)
{
    const float* feat_s     = (const float*)d_in[0];
    const float* feat_t     = (const float*)d_in[1];
    const void*  idx        = d_in[2];
    const void*  sample_idx = d_in[3];
    const float* mem_s      = (const float*)d_in[4];
    const float* mem_t      = (const float*)d_in[5];
    float* out = (float*)d_out;

    k_init<<<1, 32>>>((const int*)sample_idx);

    // 2*PER items, 8 warps/block, UNROLL items/warp
    // 2*PER = 1,048,704 = 16,386 * 8 * 8 exactly
    k_contrast<<<(unsigned)(2 * PER / (8 * UNROLL)), 256>>>(
        mem_s, mem_t, feat_s, feat_t, sample_idx, out);

    k_sum<<<512, 256>>>(out);

    k_scale<<<(unsigned)((2 * PER + 255) / 256), 256>>>(out);

    const long long n4 = NDATA * FEAT / 4;   // 32M float4 per bank
    k_copy<<<2368, 256>>>((const float4*)mem_s, (const float4*)mem_t,
                          (float4*)(out + MEM_S_OFF), (float4*)(out + MEM_T_OFF), n4);

    k_update<<<128, 128>>>(mem_s, mem_t, feat_s, feat_t, idx, out);
}